// round 7
// baseline (speedup 1.0000x reference)
#include <cuda_runtime.h>
#include <math.h>

#define B   16
#define CI  64
#define CO  64
#define H   256
#define W   256
#define MH  8
#define MW  12
#define NPART 8
#define S1  (1.0f/256.0f)
#define S2  (1.0f/256.0f)

// ---------- device scratch ----------
__device__ float d_ctab[MW*W];           // cos(2*pi*ky*w/256)
__device__ float d_stab[MW*W];           // sin
__device__ float d_hc[MH*H];             // cos(2*pi*kx*h/256)
__device__ float d_hs[MH*H];
__device__ float d_tw2[24*128];          // folded fwd twiddles [slot][w], pre-scaled S1, sin negated
__device__ float d_Xp[(size_t)B*96*CI*NPART*2];
__device__ float d_Y[(size_t)B*CO*96*2];
__device__ float d_wT[(size_t)96*CI*CO*2];

// ---------- merged init: trig tables + weight transpose ----------
__global__ void __launch_bounds__(256) init_all(const float* __restrict__ wsrc) {
    int bx = blockIdx.x;
    int t  = threadIdx.x;
    if (bx < 32) {
        int idx = bx*256 + t;
        if (idx < 3072) {
            int ky = idx >> 8, w = idx & 255;
            double a = 2.0 * (double)ky * (double)w / 256.0;
            double s, c; sincospi(a, &s, &c);
            d_ctab[idx] = (float)c; d_stab[idx] = (float)s;
        } else if (idx < 5120) {
            int j = idx - 3072;
            int kx = j >> 8, h = j & 255;
            double a = 2.0 * (double)kx * (double)h / 256.0;
            double s, c; sincospi(a, &s, &c);
            d_hc[j] = (float)c; d_hs[j] = (float)s;
        } else if (idx < 8192) {
            int j = idx - 5120;
            int s_ = j >> 7, w = j & 127;
            int ky; bool is_sin;
            if      (s_ <  6) { ky = 2*s_;          is_sin = false; }
            else if (s_ < 12) { ky = 2*(s_-6);      is_sin = true;  }
            else if (s_ < 18) { ky = 2*(s_-12)+1;   is_sin = false; }
            else              { ky = 2*(s_-18)+1;   is_sin = true;  }
            double a = 2.0 * (double)ky * (double)w / 256.0;
            double sv, cv; sincospi(a, &sv, &cv);
            d_tw2[j] = is_sin ? (float)(-S1 * sv) : (float)(S1 * cv);
        }
    } else {
        int m = bx - 32;                  // 0..95
        if (m < 96) {
            int o = t & 63;
            const float2* src = (const float2*)wsrc;
            float2* dst = (float2*)d_wT;
            #pragma unroll
            for (int i = (t >> 6); i < CI; i += 4) {
                dst[(m*CI + i)*CO + o] = src[(size_t)(i*CO + o)*96 + m];
            }
        }
    }
}

__global__ void k_filler() {}

// ---------- K1 v5: 32 rows/block, vectorized, 4 CTAs/SM ----------
// smem floats: sS[32*144] sD[32*144] stw[4*872] sT[32*25] shc2[256] shs2[256]
__global__ void __launch_bounds__(256) k1_fwd(const float* __restrict__ x) {
    extern __shared__ float sm[];
    float* sS   = sm;              // 4608
    float* sD   = sm + 4608;       // 4608
    float* stw  = sm + 9216;       // 3488
    float* sT   = sm + 12704;      // 800
    float* shc2 = sm + 13504;      // 256
    float* shs2 = sm + 13760;      // 256   -> 14016 floats = 56064 B

    int bc = blockIdx.y;
    int hb = blockIdx.x;          // 0..7
    int h0 = hb * 32;
    int t  = threadIdx.x;

    // twiddles: [kt(872)][slot(144)][qcchunk(36)][4j+r]
    for (int i = t; i < 24*128; i += 256) {
        int s_ = i >> 7, w = i & 127;
        int kt_ = s_ / 6, sl = s_ % 6;
        int qc_ = w >> 5, jj = (w >> 2) & 7, r_ = w & 3;
        stw[kt_*872 + sl*144 + qc_*36 + jj*4 + r_] = d_tw2[i];
    }
    if (t < 256) {
        int kx = t >> 5, r = t & 31;
        shc2[t] = d_hc[kx*256 + h0 + r];
        shs2[t] = d_hs[kx*256 + h0 + r];
    }
    // x fold: row stride 144, qc-chunks of 36
    const float* xb = x + ((size_t)bc*H + h0)*W;
    #pragma unroll
    for (int i = t; i < 1024; i += 256) {
        int r = i >> 5, p = i & 31;
        const float4* rp = (const float4*)(xb + (size_t)r*W);
        float4 va = rp[p];
        float4 vb = rp[p + 32];
        int off = r*144 + (p >> 3)*36 + (p & 7)*4;
        *((float4*)(sS + off)) = make_float4(va.x+vb.x, va.y+vb.y, va.z+vb.z, va.w+vb.w);
        *((float4*)(sD + off)) = make_float4(va.x-vb.x, va.y-vb.y, va.z-vb.z, va.w-vb.w);
    }
    __syncthreads();

    int qc = t & 3;          // w-chunk
    int kt = (t >> 2) & 3;   // slot group
    int rt = t >> 4;         // 0..15 -> rows 2rt, 2rt+1

    const float* xp = ((kt < 2) ? sS : sD) + rt*288 + qc*36;
    const float* tp = stw + kt*872 + qc*36;

    float acc[12];
    #pragma unroll
    for (int k = 0; k < 12; ++k) acc[k] = 0.f;

    #pragma unroll
    for (int j = 0; j < 8; ++j) {
        int off = j*4;
        float4 x0 = *((const float4*)(xp + off));
        float4 x1 = *((const float4*)(xp + 144 + off));
        float4 t0 = *((const float4*)(tp + off));
        float4 t1 = *((const float4*)(tp + 144 + off));
        float4 t2 = *((const float4*)(tp + 288 + off));
        acc[0] += x0.x*t0.x + x0.y*t0.y + x0.z*t0.z + x0.w*t0.w;
        acc[1] += x0.x*t1.x + x0.y*t1.y + x0.z*t1.z + x0.w*t1.w;
        acc[2] += x0.x*t2.x + x0.y*t2.y + x0.z*t2.z + x0.w*t2.w;
        acc[6] += x1.x*t0.x + x1.y*t0.y + x1.z*t0.z + x1.w*t0.w;
        acc[7] += x1.x*t1.x + x1.y*t1.y + x1.z*t1.z + x1.w*t1.w;
        acc[8] += x1.x*t2.x + x1.y*t2.y + x1.z*t2.z + x1.w*t2.w;
        float4 t3 = *((const float4*)(tp + 432 + off));
        float4 t4 = *((const float4*)(tp + 576 + off));
        float4 t5 = *((const float4*)(tp + 720 + off));
        acc[3] += x0.x*t3.x + x0.y*t3.y + x0.z*t3.z + x0.w*t3.w;
        acc[4] += x0.x*t4.x + x0.y*t4.y + x0.z*t4.z + x0.w*t4.w;
        acc[5] += x0.x*t5.x + x0.y*t5.y + x0.z*t5.z + x0.w*t5.w;
        acc[9]  += x1.x*t3.x + x1.y*t3.y + x1.z*t3.z + x1.w*t3.w;
        acc[10] += x1.x*t4.x + x1.y*t4.y + x1.z*t4.z + x1.w*t4.w;
        acc[11] += x1.x*t5.x + x1.y*t5.y + x1.z*t5.z + x1.w*t5.w;
    }

    #pragma unroll
    for (int k = 0; k < 12; ++k) {
        float v = acc[k];
        v += __shfl_xor_sync(0xffffffffu, v, 1);
        v += __shfl_xor_sync(0xffffffffu, v, 2);
        acc[k] = v;
    }

    if (qc == 0) {
        float* T0 = sT + (2*rt)*25 + kt*6;
        float* T1 = sT + (2*rt+1)*25 + kt*6;
        #pragma unroll
        for (int s = 0; s < 6; ++s) { T0[s] = acc[s]; T1[s] = acc[6+s]; }
    }
    __syncthreads();

    // fused partial column DFT over this block's 32 rows
    if (t < 96) {
        int kx = t / 12, ky = t % 12;
        int res = (ky & 1) ? 12 + (ky >> 1) : (ky >> 1);
        int ims = res + 6;
        float xr = 0.f, xi = 0.f;
        #pragma unroll
        for (int rr = 0; rr < 32; ++rr) {
            float tre = sT[rr*25 + res];
            float tim = sT[rr*25 + ims];
            float c = shc2[kx*32 + rr];
            float s = shs2[kx*32 + rr];
            xr += tre*c + tim*s;
            xi += tim*c - tre*s;
        }
        int b = bc >> 6, ci = bc & 63;
        ((float2*)d_Xp)[((size_t)(b*96 + t)*CI + ci)*NPART + hb] = make_float2(xr, xi);
    }
}

// ---------- K3: mode mixing ----------
__global__ void __launch_bounds__(256) k3_mix() {
    __shared__ float2 sXm[4][CI];
    int m0 = blockIdx.x * 4;
    int b  = blockIdx.y;
    int ms = threadIdx.x >> 6;
    int o  = threadIdx.x & 63;
    int m  = m0 + ms;

    const float2* Xp = (const float2*)d_Xp + ((size_t)(b*96 + m)*CI + o)*NPART;
    float xr = 0.f, xi = 0.f;
    #pragma unroll
    for (int p = 0; p < NPART; ++p) { float2 v = Xp[p]; xr += v.x; xi += v.y; }
    sXm[ms][o] = make_float2(xr, xi);
    __syncthreads();

    float yr = 0.f, yi = 0.f;
    const float2* wp = (const float2*)d_wT + (size_t)m*CI*CO + o;
    #pragma unroll 8
    for (int i = 0; i < CI; ++i) {
        float2 xv = sXm[ms][i];
        float2 wv = wp[(size_t)i*CO];
        yr += xv.x*wv.x - xv.y*wv.y;
        yi += xv.x*wv.y + xv.y*wv.x;
    }
    ((float2*)d_Y)[(size_t)(b*CO + o)*96 + m] = make_float2(yr, yi);
}

// ---------- K45: inverse column ifft + quad-folded row synthesis ----------
__global__ void __launch_bounds__(256) k45_inv(float* __restrict__ out) {
    __shared__ float sY[192];
    __shared__ float shc[MH*260];
    __shared__ float shs[MH*260];
    __shared__ __align__(16) float sC[256*28];

    int bo = blockIdx.x;
    int t  = threadIdx.x;
    float* op = out + (size_t)bo*H*W;

    for (int i = t; i < 192;   i += 256) sY[i] = d_Y[(size_t)bo*192 + i];
    for (int i = t; i < MH*H;  i += 256) {
        int kx = i >> 8, h = i & 255;
        shc[kx*260 + h] = d_hc[i];
        shs[kx*260 + h] = d_hs[i];
    }
    int wv = t & 63;
    float cr[12], sr[12];
    #pragma unroll
    for (int ky = 0; ky < 12; ++ky) {
        cr[ky] = d_ctab[ky*256 + wv];
        sr[ky] = d_stab[ky*256 + wv];
    }
    __syncthreads();

    // coefficients for h = t, plus direct w=64/192 outputs
    {
        float gre[12], gim[12];
        #pragma unroll
        for (int ky = 0; ky < 12; ++ky) { gre[ky]=0.f; gim[ky]=0.f; }
        #pragma unroll
        for (int kx = 0; kx < MH; ++kx) {
            float c = shc[kx*260 + t];
            float s = shs[kx*260 + t];
            #pragma unroll
            for (int ky = 0; ky < 12; ++ky) {
                float yr = sY[(kx*12 + ky)*2];
                float yi = sY[(kx*12 + ky)*2 + 1];
                gre[ky] += yr*c - yi*s;
                gim[ky] += yr*s + yi*c;
            }
        }
        sC[t*28 + 0] = S2*gre[0];
        #pragma unroll
        for (int ky = 1; ky < 12; ++ky) sC[t*28 + ky] = 2.f*S2*gre[ky];
        #pragma unroll
        for (int ky = 0; ky < 12; ++ky) sC[t*28 + 12 + ky] = -2.f*S2*gim[ky];

        // out[h][64] and out[h][192]: cos(ky*pi/2), sin(ky*pi/2) patterns
        float A64 = S2*gre[0] + 2.f*S2*(-gre[2] + gre[4] - gre[6] + gre[8] - gre[10]);
        float B64 = -2.f*S2*(gim[1] - gim[3] + gim[5] - gim[7] + gim[9] - gim[11]);
        op[(size_t)t*W + 64]  = A64 + B64;
        op[(size_t)t*W + 192] = A64 - B64;
    }
    __syncthreads();

    // quad synthesis: thread (wv, hg) covers w in {wv, 128-wv, 128+wv, 256-wv}, 64 h's
    int hg = t >> 6;
    #pragma unroll 4
    for (int hh = 0; hh < 64; ++hh) {
        int h = hg*64 + hh;
        const float4* p = (const float4*)(sC + h*28);
        float4 a0 = p[0], a1 = p[1], a2 = p[2];
        float4 b0 = p[3], b1 = p[4], b2 = p[5];
        float CE = a0.x*cr[0] + a0.z*cr[2] + a1.x*cr[4] + a1.z*cr[6] + a2.x*cr[8] + a2.z*cr[10];
        float CO_ = a0.y*cr[1] + a0.w*cr[3] + a1.y*cr[5] + a1.w*cr[7] + a2.y*cr[9] + a2.w*cr[11];
        float SE = b0.x*sr[0] + b0.z*sr[2] + b1.x*sr[4] + b1.z*sr[6] + b2.x*sr[8] + b2.z*sr[10];
        float SO = b0.y*sr[1] + b0.w*sr[3] + b1.y*sr[5] + b1.w*sr[7] + b2.y*sr[9] + b2.w*sr[11];
        float cp = CE + CO_, cm = CE - CO_;
        float sp = SE + SO,  sq = SE - SO;
        float* row = op + (size_t)h*W;
        row[wv]        = cp + sp;
        row[128 + wv]  = cm + sq;
        if (wv) {
            row[128 - wv] = cm - sq;
            row[256 - wv] = cp - sp;
        }
    }
}

// ---------- launch ----------
extern "C" void kernel_launch(void* const* d_in, const int* in_sizes, int n_in,
                              void* d_out, int out_size) {
    const float* x = (const float*)d_in[0];
    const float* w = (const float*)d_in[1];
    float* out = (float*)d_out;

    cudaFuncSetAttribute(k1_fwd, cudaFuncAttributeMaxDynamicSharedMemorySize, 56064);

    init_all<<<128, 256>>>(w);                    // launch 1
    k_filler<<<1, 32>>>();                        // launch 2
    k_filler<<<1, 32>>>();                        // launch 3
    k1_fwd<<<dim3(NPART, B*CI), 256, 56064>>>(x); // launch 4  <-- ncu capture slot
    k3_mix<<<dim3(24, B), 256>>>();               // launch 5
    k45_inv<<<B*CO, 256>>>(out);                  // launch 6
}

// round 9
// speedup vs baseline: 1.2731x; 1.2731x over previous
#include <cuda_runtime.h>
#include <math.h>

#define B   16
#define CI  64
#define CO  64
#define H   256
#define W   256
#define MH  8
#define MW  12
#define NPART 8
#define S1  (1.0f/256.0f)
#define S2  (1.0f/256.0f)

// ---------- device scratch ----------
__device__ float d_ctab[MW*W];
__device__ float d_stab[MW*W];
__device__ float d_hc[MH*H];
__device__ float d_hs[MH*H];
__device__ float d_tw2[24*128];          // [slot][w], pre-scaled S1, sin negated
__device__ float d_Xp[(size_t)B*96*CI*NPART*2];
__device__ float d_Y[(size_t)B*CO*96*2];
__device__ float d_wT[(size_t)96*CI*CO*2];

// ---------- merged init ----------
__global__ void __launch_bounds__(256) init_all(const float* __restrict__ wsrc) {
    int bx = blockIdx.x;
    int t  = threadIdx.x;
    if (bx < 32) {
        int idx = bx*256 + t;
        if (idx < 3072) {
            int ky = idx >> 8, w = idx & 255;
            double a = 2.0 * (double)ky * (double)w / 256.0;
            double s, c; sincospi(a, &s, &c);
            d_ctab[idx] = (float)c; d_stab[idx] = (float)s;
        } else if (idx < 5120) {
            int j = idx - 3072;
            int kx = j >> 8, h = j & 255;
            double a = 2.0 * (double)kx * (double)h / 256.0;
            double s, c; sincospi(a, &s, &c);
            d_hc[j] = (float)c; d_hs[j] = (float)s;
        } else if (idx < 8192) {
            int j = idx - 5120;
            int s_ = j >> 7, w = j & 127;
            int ky; bool is_sin;
            if      (s_ <  6) { ky = 2*s_;          is_sin = false; }
            else if (s_ < 12) { ky = 2*(s_-6);      is_sin = true;  }
            else if (s_ < 18) { ky = 2*(s_-12)+1;   is_sin = false; }
            else              { ky = 2*(s_-18)+1;   is_sin = true;  }
            double a = 2.0 * (double)ky * (double)w / 256.0;
            double sv, cv; sincospi(a, &sv, &cv);
            d_tw2[j] = is_sin ? (float)(-S1 * sv) : (float)(S1 * cv);
        }
    } else {
        int m = bx - 32;
        if (m < 96) {
            int o = t & 63;
            const float2* src = (const float2*)wsrc;
            float2* dst = (float2*)d_wT;
            #pragma unroll
            for (int i = (t >> 6); i < CI; i += 4) {
                dst[(m*CI + i)*CO + o] = src[(size_t)(i*CO + o)*96 + m];
            }
        }
    }
}

__global__ void k_filler() {}

// ---------- K1 v6: 32 rows/block, 4r x 6s scalar tile, conflict-free, 4 CTAs/SM ----------
// word offsets: sS=0 (4224), sD=4232 (4224), stw=8456 (3168), sT=11624 (800),
//               shc2=12424 (256), shs2=12680 (256)  -> 12936 words = 51744 B
#define OFF_SD   4232
#define OFF_TW   8456
#define OFF_T    11624
#define OFF_HC   12424
#define OFF_HS   12680
__global__ void __launch_bounds__(256) k1_fwd(const float* __restrict__ x) {
    extern __shared__ float sm[];
    float* sS   = sm;
    float* sD   = sm + OFF_SD;
    float* stw  = sm + OFF_TW;
    float* sT   = sm + OFF_T;
    float* shc2 = sm + OFF_HC;
    float* shs2 = sm + OFF_HS;

    int bc = blockIdx.y;
    int hb = blockIdx.x;          // 0..7
    int h0 = hb * 32;
    int t  = threadIdx.x;

    // twiddles: [slot][w] stride 132
    for (int i = t; i < 24*128; i += 256) {
        int s_ = i >> 7, w = i & 127;
        stw[s_*132 + w] = d_tw2[i];
    }
    if (t < 256) {
        int kx = t >> 5, r = t & 31;
        shc2[t] = d_hc[kx*256 + h0 + r];
        shs2[t] = d_hs[kx*256 + h0 + r];
    }
    // x fold into sS/sD, row stride 132
    const float* xb = x + ((size_t)bc*H + h0)*W;
    #pragma unroll
    for (int i = t; i < 1024; i += 256) {
        int r = i >> 5, p = i & 31;
        const float4* rp = (const float4*)(xb + (size_t)r*W);
        float4 va = rp[p];
        float4 vb = rp[p + 32];
        int off = r*132 + p*4;
        *((float4*)(sS + off)) = make_float4(va.x+vb.x, va.y+vb.y, va.z+vb.z, va.w+vb.w);
        *((float4*)(sD + off)) = make_float4(va.x-vb.x, va.y-vb.y, va.z-vb.z, va.w-vb.w);
    }
    __syncthreads();

    int qc = t & 7;          // lane bits 0-2: w phase
    int kt = (t >> 3) & 3;   // lane bits 3-4: slot group
    int rt = t >> 5;         // warp id: row tile (4 rows)

    const float* xp = ((kt < 2) ? sS : sD) + rt*4*132;
    const float* tp = stw + kt*6*132;

    float acc[24];
    #pragma unroll
    for (int k = 0; k < 24; ++k) acc[k] = 0.f;

    #pragma unroll 4
    for (int j = 0; j < 16; ++j) {
        int w = qc + 8*j;
        float x0 = xp[w];
        float x1 = xp[132 + w];
        float x2 = xp[264 + w];
        float x3 = xp[396 + w];
        float t0 = tp[w];
        float t1 = tp[132 + w];
        float t2 = tp[264 + w];
        float t3 = tp[396 + w];
        float t4 = tp[528 + w];
        float t5 = tp[660 + w];

        acc[0]  += x0*t0; acc[1]  += x0*t1; acc[2]  += x0*t2;
        acc[3]  += x0*t3; acc[4]  += x0*t4; acc[5]  += x0*t5;
        acc[6]  += x1*t0; acc[7]  += x1*t1; acc[8]  += x1*t2;
        acc[9]  += x1*t3; acc[10] += x1*t4; acc[11] += x1*t5;
        acc[12] += x2*t0; acc[13] += x2*t1; acc[14] += x2*t2;
        acc[15] += x2*t3; acc[16] += x2*t4; acc[17] += x2*t5;
        acc[18] += x3*t0; acc[19] += x3*t1; acc[20] += x3*t2;
        acc[21] += x3*t3; acc[22] += x3*t4; acc[23] += x3*t5;
    }

    // reduce across qc (lane bits 0..2)
    #pragma unroll
    for (int k = 0; k < 24; ++k) {
        float v = acc[k];
        v += __shfl_xor_sync(0xffffffffu, v, 1);
        v += __shfl_xor_sync(0xffffffffu, v, 2);
        v += __shfl_xor_sync(0xffffffffu, v, 4);
        acc[k] = v;
    }

    if (qc == 0) {
        #pragma unroll
        for (int rr = 0; rr < 4; ++rr) {
            float* Trow = sT + (rt*4 + rr)*25 + kt*6;
            #pragma unroll
            for (int s = 0; s < 6; ++s) Trow[s] = acc[rr*6 + s];
        }
    }
    __syncthreads();

    // fused partial column DFT over 32 rows
    if (t < 96) {
        int kx = t / 12, ky = t % 12;
        int res = (ky & 1) ? 12 + (ky >> 1) : (ky >> 1);
        int ims = res + 6;
        float xr = 0.f, xi = 0.f;
        #pragma unroll
        for (int rr = 0; rr < 32; ++rr) {
            float tre = sT[rr*25 + res];
            float tim = sT[rr*25 + ims];
            float c = shc2[kx*32 + rr];
            float s = shs2[kx*32 + rr];
            xr += tre*c + tim*s;
            xi += tim*c - tre*s;
        }
        int b = bc >> 6, ci = bc & 63;
        ((float2*)d_Xp)[((size_t)(b*96 + t)*CI + ci)*NPART + hb] = make_float2(xr, xi);
    }
}

// ---------- K3: mode mixing ----------
__global__ void __launch_bounds__(256) k3_mix() {
    __shared__ float2 sXm[4][CI];
    int m0 = blockIdx.x * 4;
    int b  = blockIdx.y;
    int ms = threadIdx.x >> 6;
    int o  = threadIdx.x & 63;
    int m  = m0 + ms;

    const float2* Xp = (const float2*)d_Xp + ((size_t)(b*96 + m)*CI + o)*NPART;
    float xr = 0.f, xi = 0.f;
    #pragma unroll
    for (int p = 0; p < NPART; ++p) { float2 v = Xp[p]; xr += v.x; xi += v.y; }
    sXm[ms][o] = make_float2(xr, xi);
    __syncthreads();

    float yr = 0.f, yi = 0.f;
    const float2* wp = (const float2*)d_wT + (size_t)m*CI*CO + o;
    #pragma unroll 8
    for (int i = 0; i < CI; ++i) {
        float2 xv = sXm[ms][i];
        float2 wv = wp[(size_t)i*CO];
        yr += xv.x*wv.x - xv.y*wv.y;
        yi += xv.x*wv.y + xv.y*wv.x;
    }
    ((float2*)d_Y)[(size_t)(b*CO + o)*96 + m] = make_float2(yr, yi);
}

// ---------- K45: inverse column ifft + quad-folded row synthesis ----------
__global__ void __launch_bounds__(256) k45_inv(float* __restrict__ out) {
    __shared__ float sY[192];
    __shared__ float shc[MH*260];
    __shared__ float shs[MH*260];
    __shared__ __align__(16) float sC[256*28];

    int bo = blockIdx.x;
    int t  = threadIdx.x;
    float* op = out + (size_t)bo*H*W;

    for (int i = t; i < 192;   i += 256) sY[i] = d_Y[(size_t)bo*192 + i];
    for (int i = t; i < MH*H;  i += 256) {
        int kx = i >> 8, h = i & 255;
        shc[kx*260 + h] = d_hc[i];
        shs[kx*260 + h] = d_hs[i];
    }
    int wv = t & 63;
    float cr[12], sr[12];
    #pragma unroll
    for (int ky = 0; ky < 12; ++ky) {
        cr[ky] = d_ctab[ky*256 + wv];
        sr[ky] = d_stab[ky*256 + wv];
    }
    __syncthreads();

    {
        float gre[12], gim[12];
        #pragma unroll
        for (int ky = 0; ky < 12; ++ky) { gre[ky]=0.f; gim[ky]=0.f; }
        #pragma unroll
        for (int kx = 0; kx < MH; ++kx) {
            float c = shc[kx*260 + t];
            float s = shs[kx*260 + t];
            #pragma unroll
            for (int ky = 0; ky < 12; ++ky) {
                float yr = sY[(kx*12 + ky)*2];
                float yi = sY[(kx*12 + ky)*2 + 1];
                gre[ky] += yr*c - yi*s;
                gim[ky] += yr*s + yi*c;
            }
        }
        sC[t*28 + 0] = S2*gre[0];
        #pragma unroll
        for (int ky = 1; ky < 12; ++ky) sC[t*28 + ky] = 2.f*S2*gre[ky];
        #pragma unroll
        for (int ky = 0; ky < 12; ++ky) sC[t*28 + 12 + ky] = -2.f*S2*gim[ky];

        float A64 = S2*gre[0] + 2.f*S2*(-gre[2] + gre[4] - gre[6] + gre[8] - gre[10]);
        float B64 = -2.f*S2*(gim[1] - gim[3] + gim[5] - gim[7] + gim[9] - gim[11]);
        op[(size_t)t*W + 64]  = A64 + B64;
        op[(size_t)t*W + 192] = A64 - B64;
    }
    __syncthreads();

    int hg = t >> 6;
    #pragma unroll 4
    for (int hh = 0; hh < 64; ++hh) {
        int h = hg*64 + hh;
        const float4* p = (const float4*)(sC + h*28);
        float4 a0 = p[0], a1 = p[1], a2 = p[2];
        float4 b0 = p[3], b1 = p[4], b2 = p[5];
        float CE = a0.x*cr[0] + a0.z*cr[2] + a1.x*cr[4] + a1.z*cr[6] + a2.x*cr[8] + a2.z*cr[10];
        float CO_ = a0.y*cr[1] + a0.w*cr[3] + a1.y*cr[5] + a1.w*cr[7] + a2.y*cr[9] + a2.w*cr[11];
        float SE = b0.x*sr[0] + b0.z*sr[2] + b1.x*sr[4] + b1.z*sr[6] + b2.x*sr[8] + b2.z*sr[10];
        float SO = b0.y*sr[1] + b0.w*sr[3] + b1.y*sr[5] + b1.w*sr[7] + b2.y*sr[9] + b2.w*sr[11];
        float cp = CE + CO_, cm = CE - CO_;
        float sp = SE + SO,  sq = SE - SO;
        float* row = op + (size_t)h*W;
        row[wv]        = cp + sp;
        row[128 + wv]  = cm + sq;
        if (wv) {
            row[128 - wv] = cm - sq;
            row[256 - wv] = cp - sp;
        }
    }
}

// ---------- launch ----------
extern "C" void kernel_launch(void* const* d_in, const int* in_sizes, int n_in,
                              void* d_out, int out_size) {
    const float* x = (const float*)d_in[0];
    const float* w = (const float*)d_in[1];
    float* out = (float*)d_out;

    cudaFuncSetAttribute(k1_fwd, cudaFuncAttributeMaxDynamicSharedMemorySize, 51744);

    init_all<<<128, 256>>>(w);                    // launch 1
    k_filler<<<1, 32>>>();                        // launch 2
    k_filler<<<1, 32>>>();                        // launch 3
    k1_fwd<<<dim3(NPART, B*CI), 256, 51744>>>(x); // launch 4  <-- ncu capture slot
    k3_mix<<<dim3(24, B), 256>>>();               // launch 5
    k45_inv<<<B*CO, 256>>>(out);                  // launch 6
}